// round 6
// baseline (speedup 1.0000x reference)
#include <cuda_runtime.h>
#include <math.h>
#include <math_constants.h>
#include <stdint.h>

#define BSZ  128
#define TLEN 500
#define ISZ  700
#define HSZ  256
#define OSZ  20
#define BJ0  0.01f

// Scratch. g_hpre layout: [b][t][n] (batch-major, as R4)
__device__ float g_hpre[(size_t)BSZ * TLEN * HSZ];
__device__ float g_wit[ISZ * HSZ];                  // W_i2h^T [700][256]
__device__ float g_wth[HSZ * HSZ];                  // W_h2h^T [j][i]

// ---------------------------------------------------------------------------
__global__ void prep_kernel(const float* __restrict__ Wi,
                            const float* __restrict__ Wh) {
    int idx = blockIdx.x * blockDim.x + threadIdx.x;
    if (idx < ISZ * HSZ) {
        int k = idx / HSZ, n = idx % HSZ;
        g_wit[idx] = Wi[n * ISZ + k];
    }
    if (idx < HSZ * HSZ) {
        int j = idx / HSZ, i = idx % HSZ;
        g_wth[idx] = Wh[i * HSZ + j];
    }
}

// ---------------------------------------------------------------------------
// Persistent GEMM (exactly R4; bitwise-identical hpre):
// g_hpre[m][n] = x[m][:].g_wit[:][n] + bi[n] + bh[n], m = b*TLEN + t
// ---------------------------------------------------------------------------
#define FMA2(acc, a, b) \
    asm("fma.rn.f32x2 %0, %1, %2, %0;" : "+l"(acc) : "l"(a), "l"(b))

#define GEMM_TILES 1000
#define GEMM_GRID  296

__global__ void __launch_bounds__(256, 2) gemm_kernel(
    const float* __restrict__ A,
    const float* __restrict__ bi,
    const float* __restrict__ bh) {
    const int N = HSZ, K = ISZ;
    __shared__ __align__(16) float As[2][8][128];
    __shared__ __align__(16) float Bs[2][8][128];

    int tid = threadIdx.x;
    int tx = tid & 15, ty = tid >> 4;
    int arow  = tid >> 1,  acol4 = (tid & 1) * 4;
    int brow  = tid >> 5,  bcol4 = (tid & 31) * 4;

    for (int tile = blockIdx.x; tile < GEMM_TILES; tile += GEMM_GRID) {
        int bm = (tile >> 1) * 128;
        int bn = (tile & 1) * 128;
        const float* Aptr = A + (size_t)(bm + arow) * K;

        unsigned long long acc2[8][4];
#pragma unroll
        for (int i = 0; i < 8; i++)
#pragma unroll
            for (int j = 0; j < 4; j++) acc2[i][j] = 0ull;

        {
            float4 av = make_float4(0.f, 0.f, 0.f, 0.f);
            float4 bv = make_float4(0.f, 0.f, 0.f, 0.f);
            if (acol4 < K) av = *(const float4*)(Aptr + acol4);
            if (brow  < K) bv = *(const float4*)(g_wit + (size_t)brow * N + bn + bcol4);
            As[0][acol4 + 0][arow] = av.x;
            As[0][acol4 + 1][arow] = av.y;
            As[0][acol4 + 2][arow] = av.z;
            As[0][acol4 + 3][arow] = av.w;
            *(float4*)&Bs[0][brow][bcol4] = bv;
        }
        __syncthreads();

        int p = 0;
        for (int k0 = 0; k0 < K; k0 += 8) {
            bool more = (k0 + 8) < K;
            float4 av2 = make_float4(0.f, 0.f, 0.f, 0.f);
            float4 bv2 = make_float4(0.f, 0.f, 0.f, 0.f);
            if (more) {
                int ac = k0 + 8 + acol4;
                int bk = k0 + 8 + brow;
                if (ac < K) av2 = *(const float4*)(Aptr + ac);
                if (bk < K) bv2 = *(const float4*)(g_wit + (size_t)bk * N + bn + bcol4);
            }
#pragma unroll
            for (int kk = 0; kk < 8; kk++) {
                float4 a0 = *(const float4*)&As[p][kk][ty * 8];
                float4 a1 = *(const float4*)&As[p][kk][ty * 8 + 4];
                const unsigned long long* bp =
                    (const unsigned long long*)&Bs[p][kk][tx * 8];
                unsigned long long bb0 = bp[0], bb1 = bp[1], bb2 = bp[2], bb3 = bp[3];
                float af[8] = {a0.x, a0.y, a0.z, a0.w, a1.x, a1.y, a1.z, a1.w};
#pragma unroll
                for (int i = 0; i < 8; i++) {
                    unsigned long long aa;
                    unsigned ai = __float_as_uint(af[i]);
                    asm("mov.b64 %0, {%1, %1};" : "=l"(aa) : "r"(ai));
                    FMA2(acc2[i][0], aa, bb0);
                    FMA2(acc2[i][1], aa, bb1);
                    FMA2(acc2[i][2], aa, bb2);
                    FMA2(acc2[i][3], aa, bb3);
                }
            }
            if (more) {
                As[p ^ 1][acol4 + 0][arow] = av2.x;
                As[p ^ 1][acol4 + 1][arow] = av2.y;
                As[p ^ 1][acol4 + 2][arow] = av2.z;
                As[p ^ 1][acol4 + 3][arow] = av2.w;
                *(float4*)&Bs[p ^ 1][brow][bcol4] = bv2;
            }
            __syncthreads();
            p ^= 1;
        }

        float biasv[8];
#pragma unroll
        for (int j = 0; j < 8; j++) {
            int n = bn + tx * 8 + j;
            biasv[j] = bi[n] + bh[n];
        }
#pragma unroll
        for (int i = 0; i < 8; i++) {
            size_t m = (size_t)(bm + ty * 8 + i);
            float r[8];
#pragma unroll
            for (int j = 0; j < 4; j++) {
                unsigned lo, hi;
                asm("mov.b64 {%0, %1}, %2;" : "=r"(lo), "=r"(hi) : "l"(acc2[i][j]));
                r[2 * j]     = __uint_as_float(lo) + biasv[2 * j];
                r[2 * j + 1] = __uint_as_float(hi) + biasv[2 * j + 1];
            }
            float4 v0 = make_float4(r[0], r[1], r[2], r[3]);
            float4 v1 = make_float4(r[4], r[5], r[6], r[7]);
            *(float4*)(g_hpre + m * HSZ + bn + tx * 8)     = v0;
            *(float4*)(g_hpre + m * HSZ + bn + tx * 8 + 4) = v1;
        }
    }
}

// ---------------------------------------------------------------------------
// Scan: cluster of 2 CTAs per batch pair. 576 threads:
//  wid 0-7  : hidden half-0 (sums lst[0,m))     -> does ALIF/ballot
//  wid 8-15 : hidden half-1 (sums lst[m,cnt))   -> writes partial to smem
//  wid 16/17: output warps A/B (same half split for batch r)
// ---------------------------------------------------------------------------
#define NTH 576
#define SCAN_SMEM_FLOATS 39746   // 158,984 bytes

__device__ __forceinline__ void st_peer_u32(uint32_t local_addr, uint32_t rank,
                                            uint32_t val) {
    asm volatile(
        "{.reg .b32 ra; mapa.shared::cluster.u32 ra, %0, %1;"
        " st.shared::cluster.b32 [ra], %2;}"
        :: "r"(local_addr), "r"(rank), "r"(val) : "memory");
}

__device__ __forceinline__ void mbar_arrive_local(uint32_t mbar) {
    asm volatile("mbarrier.arrive.release.cta.shared::cta.b64 _, [%0];"
                 :: "r"(mbar) : "memory");
}

__device__ __forceinline__ void mbar_arrive_peer(uint32_t mbar, uint32_t rank) {
    asm volatile(
        "{.reg .b32 ra; mapa.shared::cluster.u32 ra, %0, %1;"
        " mbarrier.arrive.release.cluster.shared::cluster.b64 _, [ra];}"
        :: "r"(mbar), "r"(rank) : "memory");
}

__device__ __forceinline__ void mbar_wait_parity(uint32_t mbar, uint32_t parity) {
    uint32_t done;
    asm volatile(
        "{\n\t.reg .pred p;\n\t"
        "mbarrier.try_wait.parity.acquire.cluster.shared::cta.b64 p, [%1], %2;\n\t"
        "selp.b32 %0, 1, 0, p;\n\t}"
        : "=r"(done) : "r"(mbar), "r"(parity) : "memory");
    if (!done) {
        asm volatile(
            "{\n\t.reg .pred P1;\n\t"
            "WL_%=:\n\t"
            "mbarrier.try_wait.parity.acquire.cluster.shared::cta.b64 P1, [%0], %1, 0x989680;\n\t"
            "@P1 bra.uni WD_%=;\n\t"
            "bra.uni WL_%=;\n\t"
            "WD_%=:\n\t}"
            :: "r"(mbar), "r"(parity) : "memory");
    }
}

__device__ __forceinline__ uint32_t smem_u32(const void* p) {
    uint32_t a;
    asm("{ .reg .u64 t; cvta.to.shared.u64 t, %1; cvt.u32.u64 %0, t; }"
        : "=r"(a) : "l"(p));
    return a;
}

#define TREE8(w0,w1,w2,w3,w4,w5,w6,w7) \
    (((w0 + w1) + (w2 + w3)) + ((w4 + w5) + (w6 + w7)))

// Sum w[lst[i]*stride] for i in [i0,i1): 8-wide trees in order, idx-prefetched.
__device__ __forceinline__ float sum_list(const float* __restrict__ w,
                                          const int* __restrict__ lst,
                                          int i0, int i1, int stride) {
    float racc = 0.f;
    int i = i0;
    if (i + 8 <= i1) {
        int4 ja = *(const int4*)(lst + i);
        int4 jb = *(const int4*)(lst + i + 4);
#pragma unroll 1
        for (; i + 16 <= i1; i += 8) {
            int4 jc = *(const int4*)(lst + i + 8);
            int4 jd = *(const int4*)(lst + i + 12);
            float w0 = w[ja.x * stride], w1 = w[ja.y * stride];
            float w2 = w[ja.z * stride], w3 = w[ja.w * stride];
            float w4 = w[jb.x * stride], w5 = w[jb.y * stride];
            float w6 = w[jb.z * stride], w7 = w[jb.w * stride];
            racc += TREE8(w0, w1, w2, w3, w4, w5, w6, w7);
            ja = jc; jb = jd;
        }
        {
            float w0 = w[ja.x * stride], w1 = w[ja.y * stride];
            float w2 = w[ja.z * stride], w3 = w[ja.w * stride];
            float w4 = w[jb.x * stride], w5 = w[jb.y * stride];
            float w6 = w[jb.z * stride], w7 = w[jb.w * stride];
            racc += TREE8(w0, w1, w2, w3, w4, w5, w6, w7);
            i += 8;
        }
    }
#pragma unroll 1
    for (; i < i1; ++i)
        racc += w[lst[i] * stride];
    return racc;
}

__global__ void __launch_bounds__(NTH, 1) __cluster_dims__(2, 1, 1)
scan_kernel(const float* __restrict__ Wo,
            const float* __restrict__ bo_bias,
            const float* __restrict__ tau_adp_o,
            const float* __restrict__ tau_m_h,
            const float* __restrict__ tau_m_o,
            const float* __restrict__ h0,
            const float* __restrict__ o0,
            float* __restrict__ out)
{
    extern __shared__ float smf[];
    float*    s_wt    = smf;                        // [256][128]
    float*    s_woT   = smf + 32768;                // [256][20]
    float*    s_spk0  = smf + 37888;                // [2][256]
    int*      s_idx   = (int*)(smf + 38400);        // [2 par][2 batch][256]
    float*    s_part  = smf + 39424;                // [2][128] hidden partials
    float*    s_opart = smf + 39680;                // [32] output partials
    unsigned* s_bal   = (unsigned*)(smf + 39712);   // [2 par][16]
    unsigned long long* s_mbar = (unsigned long long*)(smf + 39744);

    const int tid  = threadIdx.x;
    const int lane = tid & 31;
    const int wid  = tid >> 5;
    const int r    = blockIdx.x & 1;
    const int b0   = blockIdx.x & ~1;
    const bool hid0 = (wid < 8);
    const bool hid1 = (wid >= 8 && wid < 16);
    const bool outw = (wid >= 16);

    for (int i = tid; i < 8192; i += NTH) {
        int j = i >> 5, c = i & 31;
        ((float4*)s_wt)[i] =
            *(const float4*)(g_wth + (size_t)j * HSZ + r * 128 + c * 4);
    }
    for (int i = tid; i < OSZ * HSZ; i += NTH) {
        int o = i >> 8, j = i & 255;
        s_woT[j * OSZ + o] = Wo[i];
    }
    for (int i = tid; i < 2 * HSZ; i += NTH) {
        int bl2 = i >> 8, j = i & 255;
        s_spk0[i] = h0[(size_t)(b0 + bl2) * HSZ + j];
    }
    if (tid == 0) {
        asm volatile("mbarrier.init.shared.b64 [%0], %1;"
                     :: "r"(smem_u32(s_mbar)), "r"(16u) : "memory");
    }

    // hidden mapping: within each half, 256 threads = (bl = (tid>>7)&1, il)
    const int bl = (tid >> 7) & 1;
    const int il = tid & 127;
    const int q  = (wid & 3);
    const int col = r * 128 + il;
    const int gw  = r * 4 + q;             // ballot word within batch (hid0)

    float a_h = 0.f, one_m_ah = 0.f, h_mem = 0.f, spf = 0.f;
    if (hid0) {
        a_h = expf(-1.f / tau_m_h[col]);
        one_m_ah = 1.f - a_h;
        h_mem = h0[(size_t)(b0 + bl) * HSZ + col];
        spf = h_mem;
    }

    float o_mem = 0.f, o_spk = 0.f, bo = 0.f;
    float alpha_o = 0.f, ro_o = 0.f, one_m_ao = 0.f, one_m_ro = 0.f, bias_o = 0.f;
    if (wid == 16 && lane < OSZ) {
        o_mem    = o0[(size_t)blockIdx.x * OSZ + lane];
        o_spk    = o_mem;
        bo       = BJ0;
        alpha_o  = expf(-1.f / tau_m_o[lane]);
        ro_o     = expf(-1.f / tau_adp_o[lane]);
        one_m_ao = 1.f - alpha_o;
        one_m_ro = 1.f - ro_o;
        bias_o   = bo_bias[lane];
    }
    __syncthreads();
    asm volatile("barrier.cluster.arrive.aligned;" ::: "memory");
    asm volatile("barrier.cluster.wait.aligned;" ::: "memory");

    const float* hp = g_hpre + ((size_t)(b0 + bl) * TLEN) * HSZ + col;
    const float* wcol = s_wt + il;
    float pre = hid0 ? __ldcs(hp) : 0.f;
    const uint32_t bal_base = smem_u32(s_bal);
    const uint32_t mbar_u32 = smem_u32(s_mbar);
    int cntA[2] = {0, 0};

#pragma unroll 1
    for (int t = 0; t <= TLEN; ++t) {
        // ---- wait ballots(t-1); scatter both batches (512 threads) ----
        if (t >= 1) {
            mbar_wait_parity(mbar_u32, (t - 1) & 1);
            const unsigned* wp0 = s_bal + ((t - 1) & 1) * 16;
            int* idx_buf = s_idx + (t & 1) * 512;
            {
                // everyone computes both counts (needed by all roles)
#pragma unroll
                for (int bb = 0; bb < 2; bb++) {
                    int tot = 0;
#pragma unroll
                    for (int k2 = 0; k2 < 8; k2++) tot += __popc(wp0[bb * 8 + k2]);
                    cntA[bb] = tot;
                }
            }
            if (tid < 512) {
                int bb = tid >> 8;          // batch
                int n  = tid & 255;         // candidate neuron
                const unsigned* wp = wp0 + bb * 8;
                int wi = n >> 5, bit = n & 31;
                unsigned myw = wp[wi];
                if ((myw >> bit) & 1u) {
                    int pos = 0;
#pragma unroll
                    for (int k2 = 0; k2 < 8; k2++)
                        if (k2 < wi) pos += __popc(wp[k2]);
                    pos += __popc(myw & ((1u << bit) - 1u));
                    idx_buf[bb * HSZ + pos] = n;
                }
            }
        }
        __syncthreads();

        // ---- gather phase (all roles in parallel) ----
        float part = 0.f;
        if (t < TLEN && !outw) {
            if (t == 0) {
                const float* sp0 = s_spk0 + bl * HSZ;
                int j0 = hid0 ? 0 : 128;
                int j1 = j0 + 128;
#pragma unroll 8
                for (int j = j0; j < j1; ++j)
                    part += wcol[j * 128] * sp0[j];
            } else {
                const int* lst = s_idx + (t & 1) * 512 + bl * HSZ;
                const int cnt = cntA[bl];
                const int m = (cnt >> 1) & ~7;
                part = hid0 ? sum_list(wcol, lst, 0, m, 128)
                            : sum_list(wcol, lst, m, cnt, 128);
            }
            if (hid1) s_part[bl * 128 + il] = part;
        }
        float opart = 0.f;
        if (outw && t >= 1 && lane < OSZ) {
            const int* lst = s_idx + (t & 1) * 512 + r * HSZ;
            const int cnt = cntA[r];
            const int m = (cnt >> 1) & ~7;
            opart = (wid == 16) ? sum_list(s_woT + lane, lst, 0, m, OSZ)
                                : sum_list(s_woT + lane, lst, m, cnt, OSZ);
            if (wid == 17) s_opart[lane] = opart;
        }
        __syncthreads();

        // ---- hidden half-0: combine, ALIF, ballot, publish ----
        if (hid0 && t < TLEN) {
            float acc = pre;
            if (t + 1 < TLEN) pre = __ldcs(hp + (size_t)(t + 1) * HSZ);
            acc += (part + s_part[bl * 128 + il]);

            h_mem = h_mem * a_h + one_m_ah * acc - BJ0 * spf;
            int sp = (h_mem - BJ0) > 0.f;
            spf = sp ? 1.f : 0.f;
            unsigned bal = __ballot_sync(0xffffffffu, sp);
            if (lane == 0) {
                int off = (t & 1) * 16 + bl * 8 + gw;
                s_bal[off] = bal;
                st_peer_u32(bal_base + off * 4, (unsigned)(r ^ 1), bal);
                mbar_arrive_local(mbar_u32);
                mbar_arrive_peer(mbar_u32, (unsigned)(r ^ 1));
            }
        }

        // ---- output warp A: combine, ALIF_o, log-softmax, store ----
        if (wid == 16 && t >= 1) {
            const int to = t - 1;
            float om;
            if (lane < OSZ) {
                float oin = bias_o + (opart + s_opart[lane]);
                bo = ro_o * bo + one_m_ro * o_spk;
                float Bo = BJ0 + 1.8f * bo;
                o_mem = o_mem * alpha_o + one_m_ao * oin - Bo * o_spk;
                o_spk = ((o_mem - Bo) > 0.f) ? 1.f : 0.f;
                om = o_mem;
            } else {
                om = -CUDART_INF_F;
            }
            float mx = om;
#pragma unroll
            for (int off = 16; off; off >>= 1)
                mx = fmaxf(mx, __shfl_xor_sync(0xffffffffu, mx, off));
            float e = (lane < OSZ) ? expf(om - mx) : 0.f;
            float s = e;
#pragma unroll
            for (int off = 16; off; off >>= 1)
                s += __shfl_xor_sync(0xffffffffu, s, off);
            if (lane < OSZ)
                out[((size_t)blockIdx.x * OSZ + lane) * TLEN + to] = om - mx - logf(s);
        }
    }

    asm volatile("barrier.cluster.arrive.aligned;" ::: "memory");
    asm volatile("barrier.cluster.wait.aligned;" ::: "memory");
}

// ---------------------------------------------------------------------------
extern "C" void kernel_launch(void* const* d_in, const int* in_sizes, int n_in,
                              void* d_out, int out_size) {
    const float* x         = (const float*)d_in[0];
    const float* W_i2h     = (const float*)d_in[1];
    const float* b_i2h     = (const float*)d_in[2];
    const float* W_h2h     = (const float*)d_in[3];
    const float* b_h2h     = (const float*)d_in[4];
    const float* W_h2o     = (const float*)d_in[5];
    const float* b_h2o     = (const float*)d_in[6];
    const float* tau_adp_o = (const float*)d_in[8];
    const float* tau_m_h   = (const float*)d_in[9];
    const float* tau_m_o   = (const float*)d_in[10];
    const float* h0        = (const float*)d_in[11];
    const float* o0        = (const float*)d_in[12];
    float* out = (float*)d_out;

    static int inited = 0;
    if (!inited) {
        cudaFuncSetAttribute(scan_kernel,
                             cudaFuncAttributeMaxDynamicSharedMemorySize,
                             SCAN_SMEM_FLOATS * 4);
        inited = 1;
    }

    prep_kernel<<<(ISZ * HSZ + 255) / 256, 256>>>(W_i2h, W_h2h);

    gemm_kernel<<<GEMM_GRID, 256>>>(x, b_i2h, b_h2h);

    scan_kernel<<<BSZ, NTH, SCAN_SMEM_FLOATS * 4>>>(
        W_h2o, b_h2o, tau_adp_o, tau_m_h, tau_m_o, h0, o0, out);
}

// round 7
// speedup vs baseline: 1.2314x; 1.2314x over previous
#include <cuda_runtime.h>
#include <math.h>
#include <math_constants.h>
#include <stdint.h>

#define BSZ  128
#define TLEN 500
#define ISZ  700
#define HSZ  256
#define OSZ  20
#define BJ0  0.01f

// Scratch. g_hpre layout: [b][t][n]
__device__ float g_hpre[(size_t)BSZ * TLEN * HSZ];
__device__ float g_wit[ISZ * HSZ];                  // W_i2h^T [700][256]
__device__ float g_wth[HSZ * HSZ];                  // W_h2h^T [j][i]

// ---------------------------------------------------------------------------
__global__ void prep_kernel(const float* __restrict__ Wi,
                            const float* __restrict__ Wh) {
    int idx = blockIdx.x * blockDim.x + threadIdx.x;
    if (idx < ISZ * HSZ) {
        int k = idx / HSZ, n = idx % HSZ;
        g_wit[idx] = Wi[n * ISZ + k];
    }
    if (idx < HSZ * HSZ) {
        int j = idx / HSZ, i = idx % HSZ;
        g_wth[idx] = Wh[i * HSZ + j];
    }
}

// ---------------------------------------------------------------------------
// Persistent GEMM (R4 exact; bitwise-identical hpre)
// ---------------------------------------------------------------------------
#define FMA2(acc, a, b) \
    asm("fma.rn.f32x2 %0, %1, %2, %0;" : "+l"(acc) : "l"(a), "l"(b))

#define GEMM_TILES 1000
#define GEMM_GRID  296

__global__ void __launch_bounds__(256, 2) gemm_kernel(
    const float* __restrict__ A,
    const float* __restrict__ bi,
    const float* __restrict__ bh) {
    const int N = HSZ, K = ISZ;
    __shared__ __align__(16) float As[2][8][128];
    __shared__ __align__(16) float Bs[2][8][128];

    int tid = threadIdx.x;
    int tx = tid & 15, ty = tid >> 4;
    int arow  = tid >> 1,  acol4 = (tid & 1) * 4;
    int brow  = tid >> 5,  bcol4 = (tid & 31) * 4;

    for (int tile = blockIdx.x; tile < GEMM_TILES; tile += GEMM_GRID) {
        int bm = (tile >> 1) * 128;
        int bn = (tile & 1) * 128;
        const float* Aptr = A + (size_t)(bm + arow) * K;

        unsigned long long acc2[8][4];
#pragma unroll
        for (int i = 0; i < 8; i++)
#pragma unroll
            for (int j = 0; j < 4; j++) acc2[i][j] = 0ull;

        {
            float4 av = make_float4(0.f, 0.f, 0.f, 0.f);
            float4 bv = make_float4(0.f, 0.f, 0.f, 0.f);
            if (acol4 < K) av = *(const float4*)(Aptr + acol4);
            if (brow  < K) bv = *(const float4*)(g_wit + (size_t)brow * N + bn + bcol4);
            As[0][acol4 + 0][arow] = av.x;
            As[0][acol4 + 1][arow] = av.y;
            As[0][acol4 + 2][arow] = av.z;
            As[0][acol4 + 3][arow] = av.w;
            *(float4*)&Bs[0][brow][bcol4] = bv;
        }
        __syncthreads();

        int p = 0;
        for (int k0 = 0; k0 < K; k0 += 8) {
            bool more = (k0 + 8) < K;
            float4 av2 = make_float4(0.f, 0.f, 0.f, 0.f);
            float4 bv2 = make_float4(0.f, 0.f, 0.f, 0.f);
            if (more) {
                int ac = k0 + 8 + acol4;
                int bk = k0 + 8 + brow;
                if (ac < K) av2 = *(const float4*)(Aptr + ac);
                if (bk < K) bv2 = *(const float4*)(g_wit + (size_t)bk * N + bn + bcol4);
            }
#pragma unroll
            for (int kk = 0; kk < 8; kk++) {
                float4 a0 = *(const float4*)&As[p][kk][ty * 8];
                float4 a1 = *(const float4*)&As[p][kk][ty * 8 + 4];
                const unsigned long long* bp =
                    (const unsigned long long*)&Bs[p][kk][tx * 8];
                unsigned long long bb0 = bp[0], bb1 = bp[1], bb2 = bp[2], bb3 = bp[3];
                float af[8] = {a0.x, a0.y, a0.z, a0.w, a1.x, a1.y, a1.z, a1.w};
#pragma unroll
                for (int i = 0; i < 8; i++) {
                    unsigned long long aa;
                    unsigned ai = __float_as_uint(af[i]);
                    asm("mov.b64 %0, {%1, %1};" : "=l"(aa) : "r"(ai));
                    FMA2(acc2[i][0], aa, bb0);
                    FMA2(acc2[i][1], aa, bb1);
                    FMA2(acc2[i][2], aa, bb2);
                    FMA2(acc2[i][3], aa, bb3);
                }
            }
            if (more) {
                As[p ^ 1][acol4 + 0][arow] = av2.x;
                As[p ^ 1][acol4 + 1][arow] = av2.y;
                As[p ^ 1][acol4 + 2][arow] = av2.z;
                As[p ^ 1][acol4 + 3][arow] = av2.w;
                *(float4*)&Bs[p ^ 1][brow][bcol4] = bv2;
            }
            __syncthreads();
            p ^= 1;
        }

        float biasv[8];
#pragma unroll
        for (int j = 0; j < 8; j++) {
            int n = bn + tx * 8 + j;
            biasv[j] = bi[n] + bh[n];
        }
#pragma unroll
        for (int i = 0; i < 8; i++) {
            size_t m = (size_t)(bm + ty * 8 + i);
            float r[8];
#pragma unroll
            for (int j = 0; j < 4; j++) {
                unsigned lo, hi;
                asm("mov.b64 {%0, %1}, %2;" : "=r"(lo), "=r"(hi) : "l"(acc2[i][j]));
                r[2 * j]     = __uint_as_float(lo) + biasv[2 * j];
                r[2 * j + 1] = __uint_as_float(hi) + biasv[2 * j + 1];
            }
            float4 v0 = make_float4(r[0], r[1], r[2], r[3]);
            float4 v1 = make_float4(r[4], r[5], r[6], r[7]);
            *(float4*)(g_hpre + m * HSZ + bn + tx * 8)     = v0;
            *(float4*)(g_hpre + m * HSZ + bn + tx * 8 + 4) = v1;
        }
    }
}

// ---------------------------------------------------------------------------
// Scan: cluster of 2 CTAs per batch pair, 288 threads.
// NO per-step __syncthreads: each warp builds a PRIVATE spike index list
// (ascending order -> bit-identical sums). mbarrier (count=17) is the only
// cross-warp sync: 8 local hidden + 8 peer hidden + 1 local output snapshot.
// Output warp snapshots ballots, arrives early, lags one step (overlapped).
// ---------------------------------------------------------------------------
#define NTH 288
#define SCAN_SMEM_FLOATS 40740   // 162,960 bytes

__device__ __forceinline__ void st_peer_u32(uint32_t local_addr, uint32_t rank,
                                            uint32_t val) {
    asm volatile(
        "{.reg .b32 ra; mapa.shared::cluster.u32 ra, %0, %1;"
        " st.shared::cluster.b32 [ra], %2;}"
        :: "r"(local_addr), "r"(rank), "r"(val) : "memory");
}

__device__ __forceinline__ void mbar_arrive_local(uint32_t mbar) {
    asm volatile("mbarrier.arrive.release.cta.shared::cta.b64 _, [%0];"
                 :: "r"(mbar) : "memory");
}

__device__ __forceinline__ void mbar_arrive_peer(uint32_t mbar, uint32_t rank) {
    asm volatile(
        "{.reg .b32 ra; mapa.shared::cluster.u32 ra, %0, %1;"
        " mbarrier.arrive.release.cluster.shared::cluster.b64 _, [ra];}"
        :: "r"(mbar), "r"(rank) : "memory");
}

__device__ __forceinline__ void mbar_wait_parity(uint32_t mbar, uint32_t parity) {
    uint32_t done;
    asm volatile(
        "{\n\t.reg .pred p;\n\t"
        "mbarrier.try_wait.parity.acquire.cluster.shared::cta.b64 p, [%1], %2;\n\t"
        "selp.b32 %0, 1, 0, p;\n\t}"
        : "=r"(done) : "r"(mbar), "r"(parity) : "memory");
    if (!done) {
        asm volatile(
            "{\n\t.reg .pred P1;\n\t"
            "WL_%=:\n\t"
            "mbarrier.try_wait.parity.acquire.cluster.shared::cta.b64 P1, [%0], %1, 0x989680;\n\t"
            "@P1 bra.uni WD_%=;\n\t"
            "bra.uni WL_%=;\n\t"
            "WD_%=:\n\t}"
            :: "r"(mbar), "r"(parity) : "memory");
    }
}

__device__ __forceinline__ uint32_t smem_u32(const void* p) {
    uint32_t a;
    asm("{ .reg .u64 t; cvta.to.shared.u64 t, %1; cvt.u32.u64 %0, t; }"
        : "=r"(a) : "l"(p));
    return a;
}

#define TREE8(w0,w1,w2,w3,w4,w5,w6,w7) \
    (((w0 + w1) + (w2 + w3)) + ((w4 + w5) + (w6 + w7)))

// Warp-private scatter: build ascending index list of set bits in w[0..7].
// Lane l covers neurons [l*8, l*8+8). Returns total count.
__device__ __forceinline__ int warp_scatter(const unsigned w[8], int lane,
                                            int* __restrict__ seg) {
    int cnt = 0;
#pragma unroll
    for (int k2 = 0; k2 < 8; k2++) cnt += __popc(w[k2]);

    const int wi = lane >> 2;
    const int bitbase = (lane & 3) * 8;
    int pos = 0;
#pragma unroll
    for (int k2 = 0; k2 < 8; k2++)
        if (k2 < wi) pos += __popc(w[k2]);
    unsigned myw = w[wi];
    pos += __popc(myw & ((1u << bitbase) - 1u));
    unsigned byte = (myw >> bitbase) & 0xffu;
    int base_n = lane * 8;
#pragma unroll
    for (int k2 = 0; k2 < 8; k2++) {
        if (byte & (1u << k2)) seg[pos++] = base_n + k2;
    }
    __syncwarp();
    return cnt;
}

// Gather: identical arithmetic order to R4 (8-wide trees, ascending).
__device__ __forceinline__ float gather_list(const float* __restrict__ w,
                                             const int* __restrict__ lst,
                                             int cnt, int stride) {
    float racc = 0.f;
    int i = 0;
    if (cnt >= 8) {
        int4 ja = *(const int4*)(lst);
        int4 jb = *(const int4*)(lst + 4);
        float w0 = w[ja.x * stride], w1 = w[ja.y * stride];
        float w2 = w[ja.z * stride], w3 = w[ja.w * stride];
        float w4 = w[jb.x * stride], w5 = w[jb.y * stride];
        float w6 = w[jb.z * stride], w7 = w[jb.w * stride];
#pragma unroll 1
        for (i = 8; i + 8 <= cnt; i += 8) {
            int4 ja2 = *(const int4*)(lst + i);
            int4 jb2 = *(const int4*)(lst + i + 4);
            float v0 = w[ja2.x * stride], v1 = w[ja2.y * stride];
            float v2 = w[ja2.z * stride], v3 = w[ja2.w * stride];
            float v4 = w[jb2.x * stride], v5 = w[jb2.y * stride];
            float v6 = w[jb2.z * stride], v7 = w[jb2.w * stride];
            racc += TREE8(w0, w1, w2, w3, w4, w5, w6, w7);
            w0 = v0; w1 = v1; w2 = v2; w3 = v3;
            w4 = v4; w5 = v5; w6 = v6; w7 = v7;
        }
        racc += TREE8(w0, w1, w2, w3, w4, w5, w6, w7);
    }
#pragma unroll 1
    for (; i < cnt; ++i)
        racc += w[lst[i] * stride];
    return racc;
}

__global__ void __launch_bounds__(NTH, 1) __cluster_dims__(2, 1, 1)
scan_kernel(const float* __restrict__ Wo,
            const float* __restrict__ bo_bias,
            const float* __restrict__ tau_adp_o,
            const float* __restrict__ tau_m_h,
            const float* __restrict__ tau_m_o,
            const float* __restrict__ h0,
            const float* __restrict__ o0,
            float* __restrict__ out)
{
    extern __shared__ float smf[];
    float*    s_wt   = smf;                        // [256][128]
    float*    s_woT  = smf + 32768;                // [256][20]
    float*    s_spk0 = smf + 37888;                // [2][256]
    int*      s_idx  = (int*)(smf + 38400);        // [9 warps][256] private
    unsigned* s_bal  = (unsigned*)(smf + 40704);   // [2 par][16]
    unsigned long long* s_mbar = (unsigned long long*)(smf + 40736);

    const int tid  = threadIdx.x;
    const int lane = tid & 31;
    const int wid  = tid >> 5;
    const int r    = blockIdx.x & 1;
    const int b0   = blockIdx.x & ~1;
    const bool hidden = (wid < 8);

    for (int i = tid; i < 8192; i += NTH) {
        int j = i >> 5, c = i & 31;
        ((float4*)s_wt)[i] =
            *(const float4*)(g_wth + (size_t)j * HSZ + r * 128 + c * 4);
    }
    for (int i = tid; i < OSZ * HSZ; i += NTH) {
        int o = i >> 8, j = i & 255;
        s_woT[j * OSZ + o] = Wo[i];
    }
    for (int i = tid; i < 2 * HSZ; i += NTH) {
        int bl2 = i >> 8, j = i & 255;
        s_spk0[i] = h0[(size_t)(b0 + bl2) * HSZ + j];
    }
    if (tid == 0) {
        asm volatile("mbarrier.init.shared.b64 [%0], %1;"
                     :: "r"(smem_u32(s_mbar)), "r"(17u) : "memory");
    }

    const int bl = (hidden ? (tid >> 7) : 0);      // hidden batch-local
    const int il = tid & 127;
    const int q  = (wid & 3);
    const int col = r * 128 + il;
    const int gw  = r * 4 + q;
    int* myseg = s_idx + wid * 256;

    float a_h = 0.f, one_m_ah = 0.f, h_mem = 0.f, spf = 0.f;
    if (hidden) {
        a_h = expf(-1.f / tau_m_h[col]);
        one_m_ah = 1.f - a_h;
        h_mem = h0[(size_t)(b0 + bl) * HSZ + col];
        spf = h_mem;
    }

    float o_mem = 0.f, o_spk = 0.f, bo = 0.f;
    float alpha_o = 0.f, ro_o = 0.f, one_m_ao = 0.f, one_m_ro = 0.f, bias_o = 0.f;
    if (!hidden && lane < OSZ) {
        o_mem    = o0[(size_t)blockIdx.x * OSZ + lane];
        o_spk    = o_mem;
        bo       = BJ0;
        alpha_o  = expf(-1.f / tau_m_o[lane]);
        ro_o     = expf(-1.f / tau_adp_o[lane]);
        one_m_ao = 1.f - alpha_o;
        one_m_ro = 1.f - ro_o;
        bias_o   = bo_bias[lane];
    }
    __syncthreads();
    asm volatile("barrier.cluster.arrive.aligned;" ::: "memory");
    asm volatile("barrier.cluster.wait.aligned;" ::: "memory");

    const uint32_t bal_base = smem_u32(s_bal);
    const uint32_t mbar_u32 = smem_u32(s_mbar);

    if (hidden) {
        // =================== HIDDEN WARPS ===================
        const float* hp = g_hpre + ((size_t)(b0 + bl) * TLEN) * HSZ + col;
        const float* wcol = s_wt + il;
        float pre = __ldcs(hp);

#pragma unroll 1
        for (int t = 0; t < TLEN; ++t) {
            int cnt = 0;
            if (t >= 1) {
                mbar_wait_parity(mbar_u32, (t - 1) & 1);
                const unsigned* wp = s_bal + ((t - 1) & 1) * 16 + bl * 8;
                unsigned w[8];
#pragma unroll
                for (int k2 = 0; k2 < 8; k2++) w[k2] = wp[k2];
                cnt = warp_scatter(w, lane, myseg);
            }

            float acc = pre;
            if (t + 1 < TLEN) pre = __ldcs(hp + (size_t)(t + 1) * HSZ);

            float racc = 0.f;
            if (t == 0) {
                const float* sp0 = s_spk0 + bl * HSZ;
#pragma unroll 8
                for (int j = 0; j < HSZ; ++j)
                    racc += wcol[j * 128] * sp0[j];
            } else {
                racc = gather_list(wcol, myseg, cnt, 128);
            }
            acc += racc;

            h_mem = h_mem * a_h + one_m_ah * acc - BJ0 * spf;
            int sp = (h_mem - BJ0) > 0.f;
            spf = sp ? 1.f : 0.f;
            unsigned bal = __ballot_sync(0xffffffffu, sp);
            if (lane == 0) {
                int off = (t & 1) * 16 + bl * 8 + gw;
                s_bal[off] = bal;
                st_peer_u32(bal_base + off * 4, (unsigned)(r ^ 1), bal);
                mbar_arrive_local(mbar_u32);
                mbar_arrive_peer(mbar_u32, (unsigned)(r ^ 1));
            }
        }
    } else {
        // =================== OUTPUT WARP (lags one step) ===================
        if (lane == 0) mbar_arrive_local(mbar_u32);   // prime phase 0

#pragma unroll 1
        for (int t = 1; t <= TLEN; ++t) {
            mbar_wait_parity(mbar_u32, (t - 1) & 1);
            // snapshot ballots of step t-1 for batch r
            const unsigned* wp = s_bal + ((t - 1) & 1) * 16 + r * 8;
            unsigned w[8];
#pragma unroll
            for (int k2 = 0; k2 < 8; k2++) w[k2] = wp[k2];
            // free the ring slot early
            if (lane == 0 && t < TLEN) mbar_arrive_local(mbar_u32);

            int cnt = warp_scatter(w, lane, myseg);

            const int to = t - 1;
            float om;
            if (lane < OSZ) {
                float oin = bias_o + gather_list(s_woT + lane, myseg, cnt, OSZ);
                bo = ro_o * bo + one_m_ro * o_spk;
                float Bo = BJ0 + 1.8f * bo;
                o_mem = o_mem * alpha_o + one_m_ao * oin - Bo * o_spk;
                o_spk = ((o_mem - Bo) > 0.f) ? 1.f : 0.f;
                om = o_mem;
            } else {
                om = -CUDART_INF_F;
            }
            float mx = om;
#pragma unroll
            for (int off = 16; off; off >>= 1)
                mx = fmaxf(mx, __shfl_xor_sync(0xffffffffu, mx, off));
            float e = (lane < OSZ) ? __expf(om - mx) : 0.f;
            float s = e;
#pragma unroll
            for (int off = 16; off; off >>= 1)
                s += __shfl_xor_sync(0xffffffffu, s, off);
            if (lane < OSZ)
                out[((size_t)blockIdx.x * OSZ + lane) * TLEN + to] =
                    om - mx - __logf(s);
        }
    }

    asm volatile("barrier.cluster.arrive.aligned;" ::: "memory");
    asm volatile("barrier.cluster.wait.aligned;" ::: "memory");
}

// ---------------------------------------------------------------------------
extern "C" void kernel_launch(void* const* d_in, const int* in_sizes, int n_in,
                              void* d_out, int out_size) {
    const float* x         = (const float*)d_in[0];
    const float* W_i2h     = (const float*)d_in[1];
    const float* b_i2h     = (const float*)d_in[2];
    const float* W_h2h     = (const float*)d_in[3];
    const float* b_h2h     = (const float*)d_in[4];
    const float* W_h2o     = (const float*)d_in[5];
    const float* b_h2o     = (const float*)d_in[6];
    const float* tau_adp_o = (const float*)d_in[8];
    const float* tau_m_h   = (const float*)d_in[9];
    const float* tau_m_o   = (const float*)d_in[10];
    const float* h0        = (const float*)d_in[11];
    const float* o0        = (const float*)d_in[12];
    float* out = (float*)d_out;

    static int inited = 0;
    if (!inited) {
        cudaFuncSetAttribute(scan_kernel,
                             cudaFuncAttributeMaxDynamicSharedMemorySize,
                             SCAN_SMEM_FLOATS * 4);
        inited = 1;
    }

    prep_kernel<<<(ISZ * HSZ + 255) / 256, 256>>>(W_i2h, W_h2h);

    gemm_kernel<<<GEMM_GRID, 256>>>(x, b_i2h, b_h2h);

    scan_kernel<<<BSZ, NTH, SCAN_SMEM_FLOATS * 4>>>(
        W_h2o, b_h2o, tau_adp_o, tau_m_h, tau_m_o, h0, o0, out);
}